// round 12
// baseline (speedup 1.0000x reference)
#include <cuda_runtime.h>
#include <cuda_bf16.h>
#include <cstdint>
#include <math.h>

// ---------------- problem constants ----------------
#define N_TOK 4096     // B*S
#define CDIM  768      // C = nh*Dh
#define NCLU  32

// ---------------- scratch (static device memory; no allocs allowed) --------
__device__ __align__(256) float g_csum[NCLU * CDIM];
__device__ __align__(256) int8_t g_q8h[N_TOK * CDIM];          // l2norm(proxy) int8 hi
__device__ __align__(256) int8_t g_q8l[N_TOK * CDIM];          // residual (x254)
__device__ __align__(256) int8_t g_k8h[N_TOK * CDIM];          // l2norm(x) int8 hi
__device__ __align__(256) int8_t g_k8l[N_TOK * CDIM];
__device__ __align__(256) float g_sq[N_TOK];                   // row scale S/127 (proxy)
__device__ __align__(256) float g_sk[N_TOK];                   // row scale S/127 (keys)
__device__ __align__(256) __nv_bfloat16 g_v2h[CDIM * N_TOK];   // resized V, TRANSPOSED [c][n]
__device__ __align__(256) __nv_bfloat16 g_v2l[CDIM * N_TOK];
__device__ __align__(256) float g_sim[(size_t)N_TOK * N_TOK];  // similarity (fp32)
__device__ __align__(256) __nv_bfloat16 g_ph[(size_t)N_TOK * N_TOK];  // probs hi
__device__ __align__(256) __nv_bfloat16 g_pl[(size_t)N_TOK * N_TOK];  // probs lo

// ---------------- PTX helpers (all baseline sm_80 features) ----------------
__device__ __forceinline__ uint32_t smem_u32(const void* p) {
    uint32_t a;
    asm("{ .reg .u64 t; cvta.to.shared.u64 t, %1; cvt.u32.u64 %0, t; }" : "=r"(a) : "l"(p));
    return a;
}
#define CPA16(dst, src) \
    asm volatile("cp.async.cg.shared.global [%0], [%1], 16;" :: "r"(dst), "l"(src))
#define CP_COMMIT() asm volatile("cp.async.commit_group;")
#define CP_WAIT(n)  asm volatile("cp.async.wait_group %0;" :: "n"(n))

#define LDSM_X4(r0, r1, r2, r3, a) \
    asm volatile("ldmatrix.sync.aligned.m8n8.x4.shared.b16 {%0,%1,%2,%3}, [%4];" \
                 : "=r"(r0), "=r"(r1), "=r"(r2), "=r"(r3) : "r"(a))

#define MMA_BF16(c0, c1, c2, c3, a0, a1, a2, a3, b0, b1) \
    asm volatile("mma.sync.aligned.m16n8k16.row.col.f32.bf16.bf16.f32 " \
                 "{%0,%1,%2,%3}, {%4,%5,%6,%7}, {%8,%9}, {%0,%1,%2,%3};" \
                 : "+f"(c0), "+f"(c1), "+f"(c2), "+f"(c3) \
                 : "r"(a0), "r"(a1), "r"(a2), "r"(a3), "r"(b0), "r"(b1))

#define MMA_S8(c0, c1, c2, c3, a0, a1, a2, a3, b0, b1) \
    asm volatile("mma.sync.aligned.m16n8k32.row.col.s32.s8.s8.s32 " \
                 "{%0,%1,%2,%3}, {%4,%5,%6,%7}, {%8,%9}, {%0,%1,%2,%3};" \
                 : "+r"(c0), "+r"(c1), "+r"(c2), "+r"(c3) \
                 : "r"(a0), "r"(a1), "r"(a2), "r"(a3), "r"(b0), "r"(b1))

// FFMA-only exp for t <= 0 (rel err ~3e-7): exp(t) = 2^n * poly(f)
__device__ __forceinline__ float fexp(float t) {
    float z = t * 1.4426950408889634f;      // log2(e)
    z = fmaxf(z, -126.0f);
    float n = floorf(z);
    float f = z - n;
    float p = 1.33336498e-3f;
    p = fmaf(p, f, 9.61817017e-3f);
    p = fmaf(p, f, 5.55036049e-2f);
    p = fmaf(p, f, 2.40226507e-1f);
    p = fmaf(p, f, 6.93147182e-1f);
    p = fmaf(p, f, 1.0f);
    int ni = (int)n;
    float sc = __int_as_float((ni + 127) << 23);
    return p * sc;
}

// ---------------- kernel 0: zero cluster sums ----------------
__global__ void k_zero() {
    int t = blockIdx.x * 256 + threadIdx.x;
    if (t < NCLU * CDIM) g_csum[t] = 0.f;
}

// ---------------- kernel 1: bilinear resize 24x24 -> 32x32 (writes V2^T) ----
__global__ void k_resize(const float* __restrict__ vext) {
    int col = blockIdx.x;                        // 0..767
    int n = blockIdx.y * 256 + threadIdx.x;      // 0..4095
    int h = col >> 6, d = col & 63;
    int b = n >> 10, s = n & 1023, yy = s >> 5, xx = s & 31;

    float sy = 0.75f * (float)yy - 0.125f;
    float sx = 0.75f * (float)xx - 0.125f;
    float fy0 = floorf(sy), fx0 = floorf(sx);
    int y0 = (int)fy0, x0 = (int)fx0;
    float fy = sy - fy0, fx = sx - fx0;
    int y0c = max(y0, 0), y1c = min(y0 + 1, 23);
    int x0c = max(x0, 0), x1c = min(x0 + 1, 23);

    const float* base = vext + ((size_t)(b * 12 + h)) * (24 * 24 * 64) + d;
    float v00 = base[(y0c * 24 + x0c) * 64];
    float v01 = base[(y0c * 24 + x1c) * 64];
    float v10 = base[(y1c * 24 + x0c) * 64];
    float v11 = base[(y1c * 24 + x1c) * 64];
    float top = v00 + fx * (v01 - v00);
    float bot = v10 + fx * (v11 - v10);
    float val = top + fy * (bot - top);

    __nv_bfloat16 hi = __float2bfloat16(val);
    float lo = val - __bfloat162float(hi);
    g_v2h[(size_t)col * N_TOK + n] = hi;
    g_v2l[(size_t)col * N_TOK + n] = __float2bfloat16(lo);
}

// ---------------- kernel 2: per-cluster feature sums (smem-staged) ----------
__global__ __launch_bounds__(256) void k_csum(const float* __restrict__ x,
                                              const int* __restrict__ idx) {
    __shared__ float sacc[NCLU * 256];           // 32 KB
    __shared__ int sidx[256];
    int t = threadIdx.x;
    int r0 = blockIdx.x * 256;
    int c0 = blockIdx.y * 256;

#pragma unroll
    for (int c = 0; c < NCLU; c++) sacc[c * 256 + t] = 0.f;
    sidx[t] = idx[r0 + t];
    __syncthreads();

    const float* xp = x + (size_t)r0 * CDIM + c0 + t;
#pragma unroll 4
    for (int r = 0; r < 256; r++) {
        int cl = sidx[r];
        sacc[cl * 256 + t] += xp[(size_t)r * CDIM];
    }
    __syncthreads();

#pragma unroll
    for (int c = 0; c < NCLU; c++)
        atomicAdd(&g_csum[c * CDIM + c0 + t], sacc[c * 256 + t]);
}

// ---------------- kernel 3: proxy + normalization -> int8 hi/lo + scales ----
__global__ __launch_bounds__(256) void k_proxy(const float* __restrict__ x,
                                               const int* __restrict__ idx) {
    __shared__ float red[256];
    int i = blockIdx.x, t = threadIdx.x;
    int ci = __ldg(&idx[i]);
    int b = i >> 10, s = i & 1023, r = s >> 5, c = s & 31;

    int nb[8];
    int nnb = 0;
#pragma unroll
    for (int dr = -1; dr <= 1; dr++) {
#pragma unroll
        for (int dc = -1; dc <= 1; dc++) {
            if (dr == 0 && dc == 0) continue;
            int rr = r + dr, cc = c + dc;
            if (rr >= 0 && rr < 32 && cc >= 0 && cc < 32) {
                int j = (b << 10) + (rr << 5) + cc;
                if (__ldg(&idx[j]) != ci) nb[nnb++] = j;
            }
        }
    }

    float p[3], xi[3];
#pragma unroll
    for (int u = 0; u < 3; u++) {
        int col = t + u * 256;
        float v = g_csum[ci * CDIM + col];
        for (int q = 0; q < nnb; q++) v += x[nb[q] * CDIM + col];
        p[u] = v;
        xi[u] = x[i * CDIM + col];
    }

    float ssp = p[0] * p[0] + p[1] * p[1] + p[2] * p[2];
    float ssx = xi[0] * xi[0] + xi[1] * xi[1] + xi[2] * xi[2];

    red[t] = ssp; __syncthreads();
    for (int w = 128; w > 0; w >>= 1) { if (t < w) red[t] += red[t + w]; __syncthreads(); }
    float SSP = red[0]; __syncthreads();
    red[t] = ssx; __syncthreads();
    for (int w = 128; w > 0; w >>= 1) { if (t < w) red[t] += red[t + w]; __syncthreads(); }
    float SSX = red[0];

    float ip = 1.f / fmaxf(sqrtf(SSP), 1e-12f);
    float ix = 1.f / fmaxf(sqrtf(SSX), 1e-12f);

    float qv[3], kv[3];
    float mq = 0.f, mk = 0.f;
#pragma unroll
    for (int u = 0; u < 3; u++) {
        qv[u] = p[u] * ip;
        kv[u] = xi[u] * ix;
        mq = fmaxf(mq, fabsf(qv[u]));
        mk = fmaxf(mk, fabsf(kv[u]));
    }
    __syncthreads();
    red[t] = mq; __syncthreads();
    for (int w = 128; w > 0; w >>= 1) { if (t < w) red[t] = fmaxf(red[t], red[t + w]); __syncthreads(); }
    float Sq = fmaxf(red[0], 1e-12f); __syncthreads();
    red[t] = mk; __syncthreads();
    for (int w = 128; w > 0; w >>= 1) { if (t < w) red[t] = fmaxf(red[t], red[t + w]); __syncthreads(); }
    float Sk = fmaxf(red[0], 1e-12f);

    float qs = 127.f / Sq, ks = 127.f / Sk;
#pragma unroll
    for (int u = 0; u < 3; u++) {
        int col = t + u * 256;
        float uq = qv[u] * qs;
        float hq = rintf(uq);
        g_q8h[i * CDIM + col] = (int8_t)(int)hq;
        g_q8l[i * CDIM + col] = (int8_t)(int)rintf((uq - hq) * 254.f);
        float uk = kv[u] * ks;
        float hk = rintf(uk);
        g_k8h[i * CDIM + col] = (int8_t)(int)hk;
        g_k8l[i * CDIM + col] = (int8_t)(int)rintf((uk - hk) * 254.f);
    }
    if (t == 0) { g_sq[i] = Sq * (1.f / 127.f); g_sk[i] = Sk * (1.f / 127.f); }
}

// ---------------- GEMM1: SIM = QN @ KN^T via split-int8 IMMA ----------------
// CTA tile 128x64, grid (64, 32) = 2048 CTAs (6.92 full waves), occ 2.
// 8 warps (4 row x 2 col), warp tile 32x32, K-chunk 32 (one k32 IMMA step).
// smem row = 64B: [hi k0-31 | lo k0-31], granule swizzle c16 ^ ((r>>1)&3).
// 3 IMMAs per tile: hh -> acch; l*h' and h*l' both -> accx (shared s32 acc).
// sim = sq[i]*sk[j]*((float)hh + (float)cross/254).
__global__ __launch_bounds__(256, 2) void k_gemm_i8() {
    extern __shared__ char smemc[];
    const int K = CDIM;            // 768
    const int NK = K / 32;         // 24
    const int ASZ = 128 * 64;      // 8192
    const int STAGE = ASZ + 64 * 64;  // 12288

    int tid = threadIdx.x;
    int bx = blockIdx.x, by = blockIdx.y;
    uint32_t sb = smem_u32(smemc);

    // cp.async mapping: thread t -> row t>>1; half=t&1 picks hi(0)/lo(1) 32B
    int r = tid >> 1, half = tid & 1;
    size_t ga = (size_t)(by * 128 + r) * K;
    size_t gb = (size_t)(bx * 64 + (r & 63)) * K;
    int xr = (r >> 1) & 3;
    uint32_t sA0 = (uint32_t)r * 64 + (uint32_t)(((half * 2 + 0) ^ xr) << 4);
    uint32_t sA1 = (uint32_t)r * 64 + (uint32_t)(((half * 2 + 1) ^ xr) << 4);

    // ldmatrix mapping
    int l = tid & 31, w = tid >> 5;
    int wm = w & 3, wn = w >> 2;             // rows wm*32, cols wn*32
    int la = (l & 7) + ((l >> 3) & 1) * 8;   // A within-16 row
    int gA = l >> 4;                          // A k-granule 0/1
    int lb = (l & 7) + ((l >> 4) & 1) * 8;   // B within-16 n-row
    int gB = (l >> 3) & 1;                    // B k-granule 0/1

    int acch[2][4][4], accx[2][4][4];
#pragma unroll
    for (int mt = 0; mt < 2; mt++)
#pragma unroll
        for (int nt = 0; nt < 4; nt++)
#pragma unroll
            for (int q = 0; q < 4; q++) { acch[mt][nt][q] = 0; accx[mt][nt][q] = 0; }

#define ISSUE1(kt_, s_) do {                                                   \
        uint32_t base_ = sb + (uint32_t)(s_) * STAGE;                          \
        const int8_t* pa_ = (half ? g_q8l : g_q8h) + ga + (kt_) * 32;          \
        CPA16(base_ + sA0, pa_); CPA16(base_ + sA1, pa_ + 16);                 \
        if (tid < 128) {                                                       \
            const int8_t* pb_ = (half ? g_k8l : g_k8h) + gb + (kt_) * 32;      \
            CPA16(base_ + ASZ + sA0, pb_); CPA16(base_ + ASZ + sA1, pb_ + 16); \
        }                                                                      \
        CP_COMMIT();                                                           \
    } while (0)

    ISSUE1(0, 0);
    ISSUE1(1, 1);

    int scur = 0, snx2 = 2;
#pragma unroll 1
    for (int kt = 0; kt < NK; kt++) {
        if (kt == NK - 1) { CP_WAIT(0); } else { CP_WAIT(1); }
        __syncthreads();
        if (kt + 2 < NK) ISSUE1(kt + 2, snx2);

        uint32_t st = sb + (uint32_t)scur * STAGE;

        uint32_t ah[2][4], al[2][4];
#pragma unroll
        for (int mt = 0; mt < 2; mt++) {
            int ra = wm * 32 + mt * 16 + la;
            int xa = (ra >> 1) & 3;
            uint32_t rb64 = st + (uint32_t)ra * 64;
            LDSM_X4(ah[mt][0], ah[mt][1], ah[mt][2], ah[mt][3],
                    rb64 + (uint32_t)(((gA) ^ xa) << 4));
            LDSM_X4(al[mt][0], al[mt][1], al[mt][2], al[mt][3],
                    rb64 + (uint32_t)(((2 + gA) ^ xa) << 4));
        }
        uint32_t bh[2][4], bl[2][4];
#pragma unroll
        for (int g2 = 0; g2 < 2; g2++) {
            int rbn = wn * 32 + g2 * 16 + lb;
            int xb = (rbn >> 1) & 3;
            uint32_t rb64 = st + ASZ + (uint32_t)rbn * 64;
            LDSM_X4(bh[g2][0], bh[g2][1], bh[g2][2], bh[g2][3],
                    rb64 + (uint32_t)(((gB) ^ xb) << 4));
            LDSM_X4(bl[g2][0], bl[g2][1], bl[g2][2], bl[g2][3],
                    rb64 + (uint32_t)(((2 + gB) ^ xb) << 4));
        }
#pragma unroll
        for (int mt = 0; mt < 2; mt++) {
#pragma unroll
            for (int g2 = 0; g2 < 2; g2++) {
#pragma unroll
                for (int h = 0; h < 2; h++) {
                    int nt = g2 * 2 + h;
                    int* H = acch[mt][nt];
                    int* X = accx[mt][nt];
                    uint32_t b0h = bh[g2][h * 2], b1h = bh[g2][h * 2 + 1];
                    uint32_t b0l = bl[g2][h * 2], b1l = bl[g2][h * 2 + 1];
                    MMA_S8(H[0], H[1], H[2], H[3],
                           ah[mt][0], ah[mt][1], ah[mt][2], ah[mt][3], b0h, b1h);
                    MMA_S8(X[0], X[1], X[2], X[3],
                           al[mt][0], al[mt][1], al[mt][2], al[mt][3], b0h, b1h);
                    MMA_S8(X[0], X[1], X[2], X[3],
                           ah[mt][0], ah[mt][1], ah[mt][2], ah[mt][3], b0l, b1l);
                }
            }
        }
        scur = (scur == 2) ? 0 : scur + 1;
        snx2 = (snx2 == 2) ? 0 : snx2 + 1;
    }
#undef ISSUE1

    // epilogue: dequant + scale
    int l4 = l >> 2, l2 = (l & 3) * 2;
    const float inv254 = 1.f / 254.f;
#pragma unroll
    for (int mt = 0; mt < 2; mt++) {
        int row0 = by * 128 + wm * 32 + mt * 16 + l4;
        float sq0 = __ldg(&g_sq[row0]);
        float sq1 = __ldg(&g_sq[row0 + 8]);
#pragma unroll
        for (int nt = 0; nt < 4; nt++) {
            int col = bx * 64 + wn * 32 + nt * 8 + l2;
            float skx = __ldg(&g_sk[col]);
            float sky = __ldg(&g_sk[col + 1]);
            int* H = acch[mt][nt];
            int* X = accx[mt][nt];
            float f0 = (float)H[0] + (float)X[0] * inv254;
            float f1 = (float)H[1] + (float)X[1] * inv254;
            float f2 = (float)H[2] + (float)X[2] * inv254;
            float f3 = (float)H[3] + (float)X[3] * inv254;
            float2 v0 = make_float2(sq0 * skx * f0, sq0 * sky * f1);
            float2 v1 = make_float2(sq1 * skx * f2, sq1 * sky * f3);
            *(float2*)(g_sim + (size_t)row0 * N_TOK + col) = v0;
            *(float2*)(g_sim + (size_t)(row0 + 8) * N_TOK + col) = v1;
        }
    }
}

// ---------------- GEMM2: OUT = P @ V2 (split-bf16 HMMA, as R11 MODE 1) ------
// CTA tile 128x96, 8 warps, K=4096, 3-stage cp.async, occ 2, scatter epilogue.
__global__ __launch_bounds__(256, 2) void k_gemm2(float* __restrict__ outp) {
    extern __shared__ char smemc[];
    const int K = N_TOK;
    const int NK = K / 32;              // 128
    const int NTILE = 96;
    const int NP = 3, NT = 6;
    const int BH_OFF = 16384;
    const int BL_OFF = 16384 + NTILE * 64;
    const int STAGE = 16384 + 2 * NTILE * 64;   // 28672

    int tid = threadIdx.x;
    int bx = blockIdx.x, by = blockIdx.y;
    uint32_t sb = smem_u32(smemc);

    int lr = tid >> 1;
    int lc0 = (tid & 1) * 2;
    size_t ga = (size_t)(by * 128 + lr) * K;
    size_t gb = (size_t)(bx * NTILE + lr) * K;
    int xr = (lr >> 1) & 3;
    uint32_t so0 = lr * 64 + (((lc0 + 0) ^ xr) << 4);
    uint32_t so1 = lr * 64 + (((lc0 + 1) ^ xr) << 4);

    int l = tid & 31, w = tid >> 5;
    int wm = w & 3, wn = w >> 2;
    int ra = wm * 32 + (l & 15);
    int xa = (ra >> 1) & 3;
    int ab = l >> 4;
    uint32_t aoff = (uint32_t)ra * 64;
    int rb = wn * (NTILE / 2) + (l & 7) + ((l >> 4) & 1) * 8;
    int xb = (rb >> 1) & 3;
    int bb = (l >> 3) & 1;
    uint32_t boff = (uint32_t)rb * 64;

    float acc[2][NT][4];
#pragma unroll
    for (int mt = 0; mt < 2; mt++)
#pragma unroll
        for (int nt = 0; nt < NT; nt++)
#pragma unroll
            for (int q = 0; q < 4; q++) acc[mt][nt][q] = 0.f;

#define ISSUE2(kt_, s_) do {                                                   \
        uint32_t base_ = sb + (uint32_t)(s_) * STAGE;                          \
        const __nv_bfloat16* pa_  = g_ph + ga + (kt_) * 32 + lc0 * 8;          \
        const __nv_bfloat16* pal_ = g_pl + ga + (kt_) * 32 + lc0 * 8;          \
        CPA16(base_ + so0, pa_);           CPA16(base_ + so1, pa_ + 8);        \
        CPA16(base_ + 8192 + so0, pal_);   CPA16(base_ + 8192 + so1, pal_ + 8);\
        if (lr < NTILE) {                                                      \
            const __nv_bfloat16* pb_  = g_v2h + gb + (kt_) * 32 + lc0 * 8;     \
            const __nv_bfloat16* pbl_ = g_v2l + gb + (kt_) * 32 + lc0 * 8;     \
            CPA16(base_ + BH_OFF + so0, pb_);                                  \
            CPA16(base_ + BH_OFF + so1, pb_ + 8);                              \
            CPA16(base_ + BL_OFF + so0, pbl_);                                 \
            CPA16(base_ + BL_OFF + so1, pbl_ + 8);                             \
        }                                                                      \
        CP_COMMIT();                                                           \
    } while (0)

    ISSUE2(0, 0);
    ISSUE2(1, 1);

    int scur = 0, snx2 = 2;
#pragma unroll 1
    for (int kt = 0; kt < NK; kt++) {
        if (kt == NK - 1) { CP_WAIT(0); } else { CP_WAIT(1); }
        __syncthreads();
        if (kt + 2 < NK) ISSUE2(kt + 2, snx2);

        uint32_t st = sb + (uint32_t)scur * STAGE;
#pragma unroll
        for (int k16 = 0; k16 < 2; k16++) {
            uint32_t ah[2][4], al2[2][4];
#pragma unroll
            for (int mt = 0; mt < 2; mt++) {
                uint32_t ad = st + aoff + mt * 1024 + ((((2 * k16 + ab)) ^ xa) << 4);
                LDSM_X4(ah[mt][0], ah[mt][1], ah[mt][2], ah[mt][3], ad);
                LDSM_X4(al2[mt][0], al2[mt][1], al2[mt][2], al2[mt][3], ad + 8192);
            }
#pragma unroll
            for (int np = 0; np < NP; np++) {
                uint32_t bh[4], bl2[4];
                uint32_t bd = st + BH_OFF + boff + np * 1024 + ((((2 * k16 + bb)) ^ xb) << 4);
                LDSM_X4(bh[0], bh[1], bh[2], bh[3], bd);
                LDSM_X4(bl2[0], bl2[1], bl2[2], bl2[3], bd + NTILE * 64);
#pragma unroll
                for (int mt = 0; mt < 2; mt++) {
#pragma unroll
                    for (int h = 0; h < 2; h++) {
                        int nt = np * 2 + h, h2 = h * 2;
                        float* C = acc[mt][nt];
                        MMA_BF16(C[0], C[1], C[2], C[3],
                                 ah[mt][0], ah[mt][1], ah[mt][2], ah[mt][3],
                                 bh[h2], bh[h2 + 1]);
                        MMA_BF16(C[0], C[1], C[2], C[3],
                                 al2[mt][0], al2[mt][1], al2[mt][2], al2[mt][3],
                                 bh[h2], bh[h2 + 1]);
                        MMA_BF16(C[0], C[1], C[2], C[3],
                                 ah[mt][0], ah[mt][1], ah[mt][2], ah[mt][3],
                                 bl2[h2], bl2[h2 + 1]);
                    }
                }
            }
        }
        scur = (scur == 2) ? 0 : scur + 1;
        snx2 = (snx2 == 2) ? 0 : snx2 + 1;
    }
#undef ISSUE2

    int l4 = l >> 2, l2 = (l & 3) * 2;
#pragma unroll
    for (int mt = 0; mt < 2; mt++) {
#pragma unroll
        for (int nt = 0; nt < NT; nt++) {
            int row0 = by * 128 + wm * 32 + mt * 16 + l4;
            int col = bx * NTILE + wn * (NTILE / 2) + nt * 8 + l2;
            float2 v0 = make_float2(acc[mt][nt][0], acc[mt][nt][1]);
            float2 v1 = make_float2(acc[mt][nt][2], acc[mt][nt][3]);
            int o0 = (row0 & 1023) * 4 + (row0 >> 10);          // s*B + b
            int o1 = ((row0 + 8) & 1023) * 4 + ((row0 + 8) >> 10);
            *(float2*)(outp + (size_t)o0 * CDIM + col) = v0;
            *(float2*)(outp + (size_t)o1 * CDIM + col) = v1;
        }
    }
}

// ---------------- block reductions (8 warps) ----------------
__device__ __forceinline__ float bred_sum(float v, float* wred, int t) {
#pragma unroll
    for (int o = 16; o > 0; o >>= 1) v += __shfl_xor_sync(0xffffffffu, v, o);
    __syncthreads();
    if ((t & 31) == 0) wred[t >> 5] = v;
    __syncthreads();
    float s = 0.f;
#pragma unroll
    for (int i = 0; i < 8; i++) s += wred[i];
    return s;
}
__device__ __forceinline__ float bred_max(float v, float* wred, int t) {
#pragma unroll
    for (int o = 16; o > 0; o >>= 1) v = fmaxf(v, __shfl_xor_sync(0xffffffffu, v, o));
    __syncthreads();
    if ((t & 31) == 0) wred[t >> 5] = v;
    __syncthreads();
    float s = -3.402823466e38f;
#pragma unroll
    for (int i = 0; i < 8; i++) s = fmaxf(s, wred[i]);
    return s;
}

// ---------------- softmax: token_norm + cut + softmax -> hi/lo bf16 probs ---
__global__ __launch_bounds__(256) void k_softmax() {
    __shared__ float wred[8];
    int row = blockIdx.x, t = threadIdx.x;
    const float* Rp = g_sim + (size_t)row * N_TOK;

    float4 va[4];
    float s = 0.f;
#pragma unroll
    for (int u = 0; u < 4; u++) {
        va[u] = ((const float4*)Rp)[t + u * 256];
        s += (va[u].x + va[u].y) + (va[u].z + va[u].w);
    }
    float mean = fmaxf(bred_sum(s, wred, t) * (1.f / 4096.f), 0.f);

    float sub = mean * 1.2f;
    float mx = -3.402823466e38f;
#pragma unroll
    for (int u = 0; u < 4; u++) {
        va[u].x = (va[u].x - sub) * 3.0f; va[u].y = (va[u].y - sub) * 3.0f;
        va[u].z = (va[u].z - sub) * 3.0f; va[u].w = (va[u].w - sub) * 3.0f;
        mx = fmaxf(mx, fmaxf(fmaxf(va[u].x, va[u].y), fmaxf(va[u].z, va[u].w)));
    }
    float M = bred_max(mx, wred, t);

    float cut = fminf(M, 0.1f);
    const float invT = 1.f / 0.07f;
    float zs = 0.f;
#pragma unroll
    for (int u = 0; u < 4; u++) {
        va[u].x = (va[u].x < cut) ? 0.f : fexp((va[u].x - M) * invT);
        va[u].y = (va[u].y < cut) ? 0.f : fexp((va[u].y - M) * invT);
        va[u].z = (va[u].z < cut) ? 0.f : fexp((va[u].z - M) * invT);
        va[u].w = (va[u].w < cut) ? 0.f : fexp((va[u].w - M) * invT);
        zs += (va[u].x + va[u].y) + (va[u].z + va[u].w);
    }
    float inv = 1.f / bred_sum(zs, wred, t);

    __nv_bfloat16* Ph = g_ph + (size_t)row * N_TOK;
    __nv_bfloat16* Pl = g_pl + (size_t)row * N_TOK;
#pragma unroll
    for (int u = 0; u < 4; u++) {
        int c4 = t + u * 256;
        float x0 = va[u].x * inv, x1 = va[u].y * inv;
        float x2 = va[u].z * inv, x3 = va[u].w * inv;
        __nv_bfloat16 h0 = __float2bfloat16(x0);
        __nv_bfloat16 h1 = __float2bfloat16(x1);
        __nv_bfloat16 h2 = __float2bfloat16(x2);
        __nv_bfloat16 h3 = __float2bfloat16(x3);
        *(__nv_bfloat162*)(Ph + c4 * 4)     = __halves2bfloat162(h0, h1);
        *(__nv_bfloat162*)(Ph + c4 * 4 + 2) = __halves2bfloat162(h2, h3);
        __nv_bfloat16 l0 = __float2bfloat16(x0 - __bfloat162float(h0));
        __nv_bfloat16 l1 = __float2bfloat16(x1 - __bfloat162float(h1));
        __nv_bfloat16 l2b = __float2bfloat16(x2 - __bfloat162float(h2));
        __nv_bfloat16 l3 = __float2bfloat16(x3 - __bfloat162float(h3));
        *(__nv_bfloat162*)(Pl + c4 * 4)     = __halves2bfloat162(l0, l1);
        *(__nv_bfloat162*)(Pl + c4 * 4 + 2) = __halves2bfloat162(l2b, l3);
    }
}

// ---------------- launch ----------------
extern "C" void kernel_launch(void* const* d_in, const int* in_sizes, int n_in,
                              void* d_out, int out_size) {
    const float* ex = nullptr;
    const float* vext = nullptr;
    const int* idx = nullptr;
    for (int i = 0; i < n_in; i++) {
        if (in_sizes[i] == 4096) idx = (const int*)d_in[i];
        else if (in_sizes[i] == 2 * 2 * 1024 * 768) ex = (const float*)d_in[i];
        else if (in_sizes[i] == 48 * 24 * 24 * 64) vext = (const float*)d_in[i];
    }
    if (!ex || !vext || !idx) return;
    float* out = (float*)d_out;

    const int SMEM_G1 = 3 * 12288;   // int8 GEMM, 3 stages (36 KB)
    const int SMEM_G2 = 3 * 28672;   // bf16 GEMM2, 3 stages (84 KB)
    cudaFuncSetAttribute(k_gemm_i8, cudaFuncAttributeMaxDynamicSharedMemorySize, SMEM_G1);
    cudaFuncSetAttribute(k_gemm2, cudaFuncAttributeMaxDynamicSharedMemorySize, SMEM_G2);

    k_zero<<<96, 256>>>();
    k_resize<<<dim3(768, 16), 256>>>(vext);
    k_csum<<<dim3(16, 3), 256>>>(ex, idx);
    k_proxy<<<N_TOK, 256>>>(ex, idx);
    k_gemm_i8<<<dim3(64, 32), 256, SMEM_G1>>>();
    k_softmax<<<N_TOK, 256>>>();
    k_gemm2<<<dim3(8, 32), 256, SMEM_G2>>>(out);
}

// round 15
// speedup vs baseline: 2.4796x; 2.4796x over previous
#include <cuda_runtime.h>
#include <cuda_bf16.h>
#include <cstdint>
#include <math.h>

// ---------------- problem constants ----------------
#define N_TOK 4096     // B*S
#define CDIM  768      // C = nh*Dh
#define NCLU  32

// ---------------- scratch (static device memory; no allocs allowed) --------
__device__ __align__(256) float g_csum[NCLU * CDIM];
__device__ __align__(256) __nv_bfloat16 g_qnh[N_TOK * CDIM];   // l2norm(proxy) hi
__device__ __align__(256) __nv_bfloat16 g_qnl[N_TOK * CDIM];   // lo residual
__device__ __align__(256) __nv_bfloat16 g_knh[N_TOK * CDIM];   // l2norm(x) hi
__device__ __align__(256) __nv_bfloat16 g_knl[N_TOK * CDIM];
__device__ __align__(256) __nv_bfloat16 g_v2h[CDIM * N_TOK];   // resized V, TRANSPOSED [c][n]
__device__ __align__(256) __nv_bfloat16 g_v2l[CDIM * N_TOK];
__device__ __align__(256) float g_sim[(size_t)N_TOK * N_TOK];  // similarity (fp32)
__device__ __align__(256) __nv_bfloat16 g_ph[(size_t)N_TOK * N_TOK];  // probs hi
__device__ __align__(256) __nv_bfloat16 g_pl[(size_t)N_TOK * N_TOK];  // probs lo

// ---------------- PTX helpers (all baseline sm_80/89 features) -------------
__device__ __forceinline__ uint32_t smem_u32(const void* p) {
    uint32_t a;
    asm("{ .reg .u64 t; cvta.to.shared.u64 t, %1; cvt.u32.u64 %0, t; }" : "=r"(a) : "l"(p));
    return a;
}
#define CPA16(dst, src) \
    asm volatile("cp.async.cg.shared.global [%0], [%1], 16;" :: "r"(dst), "l"(src))
#define CP_COMMIT() asm volatile("cp.async.commit_group;")
#define CP_WAIT(n)  asm volatile("cp.async.wait_group %0;" :: "n"(n))

#define LDSM_X4(r0, r1, r2, r3, a) \
    asm volatile("ldmatrix.sync.aligned.m8n8.x4.shared.b16 {%0,%1,%2,%3}, [%4];" \
                 : "=r"(r0), "=r"(r1), "=r"(r2), "=r"(r3) : "r"(a))

#define MMA_BF16(c0, c1, c2, c3, a0, a1, a2, a3, b0, b1) \
    asm volatile("mma.sync.aligned.m16n8k16.row.col.f32.bf16.bf16.f32 " \
                 "{%0,%1,%2,%3}, {%4,%5,%6,%7}, {%8,%9}, {%0,%1,%2,%3};" \
                 : "+f"(c0), "+f"(c1), "+f"(c2), "+f"(c3) \
                 : "r"(a0), "r"(a1), "r"(a2), "r"(a3), "r"(b0), "r"(b1))

// FFMA-only exp for t <= 0 (rel err ~3e-7): exp(t) = 2^n * poly(f)
__device__ __forceinline__ float fexp(float t) {
    float z = t * 1.4426950408889634f;      // log2(e)
    z = fmaxf(z, -126.0f);
    float n = floorf(z);
    float f = z - n;
    float p = 1.33336498e-3f;
    p = fmaf(p, f, 9.61817017e-3f);
    p = fmaf(p, f, 5.55036049e-2f);
    p = fmaf(p, f, 2.40226507e-1f);
    p = fmaf(p, f, 6.93147182e-1f);
    p = fmaf(p, f, 1.0f);
    int ni = (int)n;
    float sc = __int_as_float((ni + 127) << 23);
    return p * sc;
}

// ---------------- kernel 0: zero cluster sums ----------------
__global__ void k_zero() {
    int t = blockIdx.x * 256 + threadIdx.x;
    if (t < NCLU * CDIM) g_csum[t] = 0.f;
}

// ---------------- kernel 1: bilinear resize 24x24 -> 32x32 (writes V2^T) ----
__global__ void k_resize(const float* __restrict__ vext) {
    int col = blockIdx.x;                        // 0..767
    int n = blockIdx.y * 256 + threadIdx.x;      // 0..4095
    int h = col >> 6, d = col & 63;
    int b = n >> 10, s = n & 1023, yy = s >> 5, xx = s & 31;

    float sy = 0.75f * (float)yy - 0.125f;
    float sx = 0.75f * (float)xx - 0.125f;
    float fy0 = floorf(sy), fx0 = floorf(sx);
    int y0 = (int)fy0, x0 = (int)fx0;
    float fy = sy - fy0, fx = sx - fx0;
    int y0c = max(y0, 0), y1c = min(y0 + 1, 23);
    int x0c = max(x0, 0), x1c = min(x0 + 1, 23);

    const float* base = vext + ((size_t)(b * 12 + h)) * (24 * 24 * 64) + d;
    float v00 = base[(y0c * 24 + x0c) * 64];
    float v01 = base[(y0c * 24 + x1c) * 64];
    float v10 = base[(y1c * 24 + x0c) * 64];
    float v11 = base[(y1c * 24 + x1c) * 64];
    float top = v00 + fx * (v01 - v00);
    float bot = v10 + fx * (v11 - v10);
    float val = top + fy * (bot - top);

    __nv_bfloat16 hi = __float2bfloat16(val);
    float lo = val - __bfloat162float(hi);
    g_v2h[(size_t)col * N_TOK + n] = hi;
    g_v2l[(size_t)col * N_TOK + n] = __float2bfloat16(lo);
}

// ---------------- kernel 2: per-cluster feature sums (smem-staged) ----------
__global__ __launch_bounds__(256) void k_csum(const float* __restrict__ x,
                                              const int* __restrict__ idx) {
    __shared__ float sacc[NCLU * 256];           // 32 KB
    __shared__ int sidx[256];
    int t = threadIdx.x;
    int r0 = blockIdx.x * 256;
    int c0 = blockIdx.y * 256;

#pragma unroll
    for (int c = 0; c < NCLU; c++) sacc[c * 256 + t] = 0.f;
    sidx[t] = idx[r0 + t];
    __syncthreads();

    // column t is owned by thread t -> no concurrent writers, plain RMW
    const float* xp = x + (size_t)r0 * CDIM + c0 + t;
#pragma unroll 4
    for (int r = 0; r < 256; r++) {
        int cl = sidx[r];
        sacc[cl * 256 + t] += xp[(size_t)r * CDIM];
    }
    __syncthreads();

#pragma unroll
    for (int c = 0; c < NCLU; c++)
        atomicAdd(&g_csum[c * CDIM + c0 + t], sacc[c * 256 + t]);
}

// ---------------- kernel 3: proxy + normalization (hi/lo bf16 out) ----------
__global__ __launch_bounds__(256) void k_proxy(const float* __restrict__ x,
                                               const int* __restrict__ idx) {
    __shared__ float red[256];
    int i = blockIdx.x, t = threadIdx.x;
    int ci = __ldg(&idx[i]);
    int b = i >> 10, s = i & 1023, r = s >> 5, c = s & 31;

    int nb[8];
    int nnb = 0;
#pragma unroll
    for (int dr = -1; dr <= 1; dr++) {
#pragma unroll
        for (int dc = -1; dc <= 1; dc++) {
            if (dr == 0 && dc == 0) continue;
            int rr = r + dr, cc = c + dc;
            if (rr >= 0 && rr < 32 && cc >= 0 && cc < 32) {
                int j = (b << 10) + (rr << 5) + cc;
                if (__ldg(&idx[j]) != ci) nb[nnb++] = j;
            }
        }
    }

    float p[3], xi[3];
#pragma unroll
    for (int u = 0; u < 3; u++) {
        int col = t + u * 256;
        float v = g_csum[ci * CDIM + col];
        for (int q = 0; q < nnb; q++) v += x[nb[q] * CDIM + col];
        p[u] = v;
        xi[u] = x[i * CDIM + col];
    }

    float ssp = p[0] * p[0] + p[1] * p[1] + p[2] * p[2];
    float ssx = xi[0] * xi[0] + xi[1] * xi[1] + xi[2] * xi[2];

    red[t] = ssp; __syncthreads();
    for (int w = 128; w > 0; w >>= 1) { if (t < w) red[t] += red[t + w]; __syncthreads(); }
    float SSP = red[0]; __syncthreads();
    red[t] = ssx; __syncthreads();
    for (int w = 128; w > 0; w >>= 1) { if (t < w) red[t] += red[t + w]; __syncthreads(); }
    float SSX = red[0];

    float ip = 1.f / fmaxf(sqrtf(SSP), 1e-12f);
    float ix = 1.f / fmaxf(sqrtf(SSX), 1e-12f);
#pragma unroll
    for (int u = 0; u < 3; u++) {
        int col = t + u * 256;
        float q = p[u] * ip;
        float k = xi[u] * ix;
        __nv_bfloat16 qh = __float2bfloat16(q);
        __nv_bfloat16 kh = __float2bfloat16(k);
        g_qnh[i * CDIM + col] = qh;
        g_qnl[i * CDIM + col] = __float2bfloat16(q - __bfloat162float(qh));
        g_knh[i * CDIM + col] = kh;
        g_knl[i * CDIM + col] = __float2bfloat16(k - __bfloat162float(kh));
    }
}

// ---------------- split-bf16 HMMA GEMM: C[M][N] = A[M][K] * B[N][K]^T -------
// MODE 0: SIM = QN @ KN^T  (K=768,  NTILE=64)  -> g_sim fp32; grid 2048 CTAs
//         (6.92 waves at occ 2 -> 98.9% wave fill vs 86.5% at NTILE=128)
// MODE 1: OUT = P  @ V2    (K=4096, NTILE=96)  -> scatter rows; 256 CTAs
// CTA tile 128 x NTILE, 8 warps (4x2), K-chunk 32, 3-stage cp.async pipeline
// with ONE __syncthreads per chunk, occ 2. XOR swizzle sw(r,c16)=c16^((r>>1)&3).
// NOTE: B row index is plain lr guarded by lr < NTILE (NO bitmask: NTILE=96
// is not a power of two; the &-mask aliased rows 32-63 onto 0-31 in R13).
template <int MODE, int NTILE>
__global__ __launch_bounds__(256, 2)
void k_gemm_mma(float* __restrict__ outp) {
    extern __shared__ char smemc[];
    const int K = (MODE == 0) ? CDIM : N_TOK;
    const int NK = K / 32;
    const int NP = NTILE / 32;          // 16-row LDSM groups per warp-col
    const int NT = 2 * NP;              // 8-col accum tiles per warp
    const int BH_OFF = 16384;
    const int BL_OFF = 16384 + NTILE * 64;
    const int STAGE = 16384 + 2 * NTILE * 64;

    const __nv_bfloat16* Ah = (MODE == 0) ? g_qnh : g_ph;
    const __nv_bfloat16* Al = (MODE == 0) ? g_qnl : g_pl;
    const __nv_bfloat16* Bh = (MODE == 0) ? g_knh : g_v2h;
    const __nv_bfloat16* Bl = (MODE == 0) ? g_knl : g_v2l;

    int tid = threadIdx.x;
    int bx = blockIdx.x, by = blockIdx.y;
    uint32_t sb = smem_u32(smemc);

    // ---- cp.async lane mapping: 2 threads/row, 2x16B each ----
    int lr = tid >> 1;                       // 0..127
    int lc0 = (tid & 1) * 2;                 // 16B-unit col 0 or 2
    size_t ga = (size_t)(by * 128 + lr) * K;
    size_t gb = (size_t)(bx * NTILE + lr) * K;   // only used under lr < NTILE
    int xr = (lr >> 1) & 3;
    uint32_t so0 = lr * 64 + (((lc0 + 0) ^ xr) << 4);
    uint32_t so1 = lr * 64 + (((lc0 + 1) ^ xr) << 4);

    // ---- ldmatrix lane mapping ----
    int l = tid & 31, w = tid >> 5;
    int wm = w & 3, wn = w >> 2;             // warp tile: rows wm*32, cols wn*(NTILE/2)
    int ra = wm * 32 + (l & 15);
    int xa = (ra >> 1) & 3;
    int ab = l >> 4;
    uint32_t aoff = (uint32_t)ra * 64;
    int rb = wn * (NTILE / 2) + (l & 7) + ((l >> 4) & 1) * 8;
    int xb = (rb >> 1) & 3;
    int bb = (l >> 3) & 1;
    uint32_t boff = (uint32_t)rb * 64;

    float acc[2][NT][4];
#pragma unroll
    for (int mt = 0; mt < 2; mt++)
#pragma unroll
        for (int nt = 0; nt < NT; nt++)
#pragma unroll
            for (int q = 0; q < 4; q++) acc[mt][nt][q] = 0.f;

#define ISSUE(kt_, s_) do {                                                    \
        uint32_t base_ = sb + (uint32_t)(s_) * STAGE;                          \
        const __nv_bfloat16* pa_  = Ah + ga + (kt_) * 32 + lc0 * 8;            \
        const __nv_bfloat16* pal_ = Al + ga + (kt_) * 32 + lc0 * 8;            \
        CPA16(base_ + so0, pa_);           CPA16(base_ + so1, pa_ + 8);        \
        CPA16(base_ + 8192 + so0, pal_);   CPA16(base_ + 8192 + so1, pal_ + 8);\
        if (lr < NTILE) {                                                      \
            const __nv_bfloat16* pb_  = Bh + gb + (kt_) * 32 + lc0 * 8;        \
            const __nv_bfloat16* pbl_ = Bl + gb + (kt_) * 32 + lc0 * 8;        \
            CPA16(base_ + BH_OFF + so0, pb_);                                  \
            CPA16(base_ + BH_OFF + so1, pb_ + 8);                              \
            CPA16(base_ + BL_OFF + so0, pbl_);                                 \
            CPA16(base_ + BL_OFF + so1, pbl_ + 8);                             \
        }                                                                      \
        CP_COMMIT();                                                           \
    } while (0)

    ISSUE(0, 0);
    ISSUE(1, 1);

    int scur = 0;    // stage of chunk kt
    int snx2 = 2;    // stage for chunk kt+2
#pragma unroll 1
    for (int kt = 0; kt < NK; kt++) {
        if (kt == NK - 1) { CP_WAIT(0); } else { CP_WAIT(1); }
        __syncthreads();
        // stage snx2 was last read at iteration kt-1; the barrier above
        // ordered those reads -> safe to overwrite, no second barrier needed.
        if (kt + 2 < NK) ISSUE(kt + 2, snx2);

        uint32_t st = sb + (uint32_t)scur * STAGE;
#pragma unroll
        for (int k16 = 0; k16 < 2; k16++) {
            uint32_t ah[2][4], al2[2][4];
#pragma unroll
            for (int mt = 0; mt < 2; mt++) {
                uint32_t ad = st + aoff + mt * 1024 + ((((2 * k16 + ab)) ^ xa) << 4);
                LDSM_X4(ah[mt][0], ah[mt][1], ah[mt][2], ah[mt][3], ad);
                LDSM_X4(al2[mt][0], al2[mt][1], al2[mt][2], al2[mt][3], ad + 8192);
            }
#pragma unroll
            for (int np = 0; np < NP; np++) {
                uint32_t bh[4], bl2[4];
                uint32_t bd = st + BH_OFF + boff + np * 1024 + ((((2 * k16 + bb)) ^ xb) << 4);
                LDSM_X4(bh[0], bh[1], bh[2], bh[3], bd);
                LDSM_X4(bl2[0], bl2[1], bl2[2], bl2[3], bd + NTILE * 64);
#pragma unroll
                for (int mt = 0; mt < 2; mt++) {
#pragma unroll
                    for (int h = 0; h < 2; h++) {
                        int nt = np * 2 + h, h2 = h * 2;
                        float* C = acc[mt][nt];
                        MMA_BF16(C[0], C[1], C[2], C[3],
                                 ah[mt][0], ah[mt][1], ah[mt][2], ah[mt][3],
                                 bh[h2], bh[h2 + 1]);
                        MMA_BF16(C[0], C[1], C[2], C[3],
                                 al2[mt][0], al2[mt][1], al2[mt][2], al2[mt][3],
                                 bh[h2], bh[h2 + 1]);
                        MMA_BF16(C[0], C[1], C[2], C[3],
                                 ah[mt][0], ah[mt][1], ah[mt][2], ah[mt][3],
                                 bl2[h2], bl2[h2 + 1]);
                    }
                }
            }
        }
        scur = (scur == 2) ? 0 : scur + 1;
        snx2 = (snx2 == 2) ? 0 : snx2 + 1;
    }
#undef ISSUE

    // ---- epilogue ----
    int l4 = l >> 2, l2 = (l & 3) * 2;
#pragma unroll
    for (int mt = 0; mt < 2; mt++) {
#pragma unroll
        for (int nt = 0; nt < NT; nt++) {
            int row0 = by * 128 + wm * 32 + mt * 16 + l4;
            int col = bx * NTILE + wn * (NTILE / 2) + nt * 8 + l2;
            float2 v0 = make_float2(acc[mt][nt][0], acc[mt][nt][1]);
            float2 v1 = make_float2(acc[mt][nt][2], acc[mt][nt][3]);
            if (MODE == 0) {
                *(float2*)(g_sim + (size_t)row0 * N_TOK + col) = v0;
                *(float2*)(g_sim + (size_t)(row0 + 8) * N_TOK + col) = v1;
            } else {
                int o0 = (row0 & 1023) * 4 + (row0 >> 10);          // s*B + b
                int o1 = ((row0 + 8) & 1023) * 4 + ((row0 + 8) >> 10);
                *(float2*)(outp + (size_t)o0 * CDIM + col) = v0;
                *(float2*)(outp + (size_t)o1 * CDIM + col) = v1;
            }
        }
    }
}

// ---------------- block reductions (8 warps) ----------------
__device__ __forceinline__ float bred_sum(float v, float* wred, int t) {
#pragma unroll
    for (int o = 16; o > 0; o >>= 1) v += __shfl_xor_sync(0xffffffffu, v, o);
    __syncthreads();
    if ((t & 31) == 0) wred[t >> 5] = v;
    __syncthreads();
    float s = 0.f;
#pragma unroll
    for (int i = 0; i < 8; i++) s += wred[i];
    return s;
}
__device__ __forceinline__ float bred_max(float v, float* wred, int t) {
#pragma unroll
    for (int o = 16; o > 0; o >>= 1) v = fmaxf(v, __shfl_xor_sync(0xffffffffu, v, o));
    __syncthreads();
    if ((t & 31) == 0) wred[t >> 5] = v;
    __syncthreads();
    float s = -3.402823466e38f;
#pragma unroll
    for (int i = 0; i < 8; i++) s = fmaxf(s, wred[i]);
    return s;
}

// ---------------- softmax: token_norm + cut + softmax -> hi/lo bf16 probs ---
// Row kept entirely in registers (16 floats/thread); FFMA-poly exp (no MUFU).
__global__ __launch_bounds__(256) void k_softmax() {
    __shared__ float wred[8];
    int row = blockIdx.x, t = threadIdx.x;
    const float* Rp = g_sim + (size_t)row * N_TOK;

    float4 va[4];
    float s = 0.f;
#pragma unroll
    for (int u = 0; u < 4; u++) {
        va[u] = ((const float4*)Rp)[t + u * 256];
        s += (va[u].x + va[u].y) + (va[u].z + va[u].w);
    }
    float mean = fmaxf(bred_sum(s, wred, t) * (1.f / 4096.f), 0.f);

    float sub = mean * 1.2f;
    float mx = -3.402823466e38f;
#pragma unroll
    for (int u = 0; u < 4; u++) {
        va[u].x = (va[u].x - sub) * 3.0f; va[u].y = (va[u].y - sub) * 3.0f;
        va[u].z = (va[u].z - sub) * 3.0f; va[u].w = (va[u].w - sub) * 3.0f;
        mx = fmaxf(mx, fmaxf(fmaxf(va[u].x, va[u].y), fmaxf(va[u].z, va[u].w)));
    }
    float M = bred_max(mx, wred, t);

    float cut = fminf(M, 0.1f);
    const float invT = 1.f / 0.07f;
    float zs = 0.f;
#pragma unroll
    for (int u = 0; u < 4; u++) {
        va[u].x = (va[u].x < cut) ? 0.f : fexp((va[u].x - M) * invT);
        va[u].y = (va[u].y < cut) ? 0.f : fexp((va[u].y - M) * invT);
        va[u].z = (va[u].z < cut) ? 0.f : fexp((va[u].z - M) * invT);
        va[u].w = (va[u].w < cut) ? 0.f : fexp((va[u].w - M) * invT);
        zs += (va[u].x + va[u].y) + (va[u].z + va[u].w);
    }
    float inv = 1.f / bred_sum(zs, wred, t);

    __nv_bfloat16* Ph = g_ph + (size_t)row * N_TOK;
    __nv_bfloat16* Pl = g_pl + (size_t)row * N_TOK;
#pragma unroll
    for (int u = 0; u < 4; u++) {
        int c4 = t + u * 256;
        float x0 = va[u].x * inv, x1 = va[u].y * inv;
        float x2 = va[u].z * inv, x3 = va[u].w * inv;
        __nv_bfloat16 h0 = __float2bfloat16(x0);
        __nv_bfloat16 h1 = __float2bfloat16(x1);
        __nv_bfloat16 h2 = __float2bfloat16(x2);
        __nv_bfloat16 h3 = __float2bfloat16(x3);
        *(__nv_bfloat162*)(Ph + c4 * 4)     = __halves2bfloat162(h0, h1);
        *(__nv_bfloat162*)(Ph + c4 * 4 + 2) = __halves2bfloat162(h2, h3);
        __nv_bfloat16 l0 = __float2bfloat16(x0 - __bfloat162float(h0));
        __nv_bfloat16 l1 = __float2bfloat16(x1 - __bfloat162float(h1));
        __nv_bfloat16 l2b = __float2bfloat16(x2 - __bfloat162float(h2));
        __nv_bfloat16 l3 = __float2bfloat16(x3 - __bfloat162float(h3));
        *(__nv_bfloat162*)(Pl + c4 * 4)     = __halves2bfloat162(l0, l1);
        *(__nv_bfloat162*)(Pl + c4 * 4 + 2) = __halves2bfloat162(l2b, l3);
    }
}

// ---------------- launch ----------------
extern "C" void kernel_launch(void* const* d_in, const int* in_sizes, int n_in,
                              void* d_out, int out_size) {
    const float* ex = nullptr;
    const float* vext = nullptr;
    const int* idx = nullptr;
    for (int i = 0; i < n_in; i++) {
        if (in_sizes[i] == 4096) idx = (const int*)d_in[i];
        else if (in_sizes[i] == 2 * 2 * 1024 * 768) ex = (const float*)d_in[i];
        else if (in_sizes[i] == 48 * 24 * 24 * 64) vext = (const float*)d_in[i];
    }
    if (!ex || !vext || !idx) return;
    float* out = (float*)d_out;

    const int SMEM_G1 = 3 * (16384 + 2 * 64 * 64);  // NTILE=64, 3 stages (72 KB)
    const int SMEM_G2 = 3 * (16384 + 2 * 96 * 64);  // NTILE=96, 3 stages (84 KB)
    cudaFuncSetAttribute(k_gemm_mma<0, 64>, cudaFuncAttributeMaxDynamicSharedMemorySize, SMEM_G1);
    cudaFuncSetAttribute(k_gemm_mma<1, 96>, cudaFuncAttributeMaxDynamicSharedMemorySize, SMEM_G2);

    k_zero<<<96, 256>>>();
    k_resize<<<dim3(768, 16), 256>>>(vext);
    k_csum<<<dim3(16, 3), 256>>>(ex, idx);
    k_proxy<<<N_TOK, 256>>>(ex, idx);
    k_gemm_mma<0, 64><<<dim3(64, 32), 256, SMEM_G1>>>(out);
    k_softmax<<<N_TOK, 256>>>();
    k_gemm_mma<1, 96><<<dim3(8, 32), 256, SMEM_G2>>>(out);
}

// round 16
// speedup vs baseline: 3.1360x; 1.2647x over previous
#include <cuda_runtime.h>
#include <cuda_fp16.h>
#include <cstdint>
#include <math.h>

// ---------------- problem constants ----------------
#define N_TOK 4096     // B*S
#define CDIM  768      // C = nh*Dh
#define NCLU  32

// ---------------- scratch (static device memory; no allocs allowed) --------
// Split-fp16 scheme: x = h + l, h=fp16(x), l=fp16(x-h).
// GEMM computes A_h*B_h + A_l*B_h = A*B_h exactly; dropped term A*l_B has
// random-sum sd ~2^-12*|A||B| ~ 1e-5 -> B-side needs NO low half at all.
__device__ __align__(256) float g_csum[NCLU * CDIM];
__device__ __align__(256) __half g_qnh[N_TOK * CDIM];          // l2norm(proxy) hi
__device__ __align__(256) __half g_qnl[N_TOK * CDIM];          // lo residual
__device__ __align__(256) __half g_knh[N_TOK * CDIM];          // l2norm(x), single fp16
__device__ __align__(256) __half g_v2h[CDIM * N_TOK];          // resized V^T, single fp16
__device__ __align__(256) float g_sim[(size_t)N_TOK * N_TOK];  // similarity (fp32)
__device__ __align__(256) __half g_ph[(size_t)N_TOK * N_TOK];  // probs hi
__device__ __align__(256) __half g_pl[(size_t)N_TOK * N_TOK];  // probs lo

// ---------------- PTX helpers (all baseline sm_80/89 features) -------------
__device__ __forceinline__ uint32_t smem_u32(const void* p) {
    uint32_t a;
    asm("{ .reg .u64 t; cvta.to.shared.u64 t, %1; cvt.u32.u64 %0, t; }" : "=r"(a) : "l"(p));
    return a;
}
#define CPA16(dst, src) \
    asm volatile("cp.async.cg.shared.global [%0], [%1], 16;" :: "r"(dst), "l"(src))
#define CP_COMMIT() asm volatile("cp.async.commit_group;")
#define CP_WAIT(n)  asm volatile("cp.async.wait_group %0;" :: "n"(n))

#define LDSM_X4(r0, r1, r2, r3, a) \
    asm volatile("ldmatrix.sync.aligned.m8n8.x4.shared.b16 {%0,%1,%2,%3}, [%4];" \
                 : "=r"(r0), "=r"(r1), "=r"(r2), "=r"(r3) : "r"(a))

#define MMA_F16(c0, c1, c2, c3, a0, a1, a2, a3, b0, b1) \
    asm volatile("mma.sync.aligned.m16n8k16.row.col.f32.f16.f16.f32 " \
                 "{%0,%1,%2,%3}, {%4,%5,%6,%7}, {%8,%9}, {%0,%1,%2,%3};" \
                 : "+f"(c0), "+f"(c1), "+f"(c2), "+f"(c3) \
                 : "r"(a0), "r"(a1), "r"(a2), "r"(a3), "r"(b0), "r"(b1))

// FFMA-only exp for t <= 0 (rel err ~3e-7): exp(t) = 2^n * poly(f)
__device__ __forceinline__ float fexp(float t) {
    float z = t * 1.4426950408889634f;      // log2(e)
    z = fmaxf(z, -126.0f);
    float n = floorf(z);
    float f = z - n;
    float p = 1.33336498e-3f;
    p = fmaf(p, f, 9.61817017e-3f);
    p = fmaf(p, f, 5.55036049e-2f);
    p = fmaf(p, f, 2.40226507e-1f);
    p = fmaf(p, f, 6.93147182e-1f);
    p = fmaf(p, f, 1.0f);
    int ni = (int)n;
    float sc = __int_as_float((ni + 127) << 23);
    return p * sc;
}

// ---------------- kernel 1: bilinear resize 24x24 -> 32x32 (writes V2^T) ----
// Also zeroes g_csum (fused so k_gemm1 lands on ncu's capture slot #4).
__global__ void k_resize(const float* __restrict__ vext) {
    if (blockIdx.y == 0 && blockIdx.x < 96) {
        g_csum[blockIdx.x * 256 + threadIdx.x] = 0.f;
    }
    int col = blockIdx.x;                        // 0..767
    int n = blockIdx.y * 256 + threadIdx.x;      // 0..4095
    int h = col >> 6, d = col & 63;
    int b = n >> 10, s = n & 1023, yy = s >> 5, xx = s & 31;

    float sy = 0.75f * (float)yy - 0.125f;
    float sx = 0.75f * (float)xx - 0.125f;
    float fy0 = floorf(sy), fx0 = floorf(sx);
    int y0 = (int)fy0, x0 = (int)fx0;
    float fy = sy - fy0, fx = sx - fx0;
    int y0c = max(y0, 0), y1c = min(y0 + 1, 23);
    int x0c = max(x0, 0), x1c = min(x0 + 1, 23);

    const float* base = vext + ((size_t)(b * 12 + h)) * (24 * 24 * 64) + d;
    float v00 = base[(y0c * 24 + x0c) * 64];
    float v01 = base[(y0c * 24 + x1c) * 64];
    float v10 = base[(y1c * 24 + x0c) * 64];
    float v11 = base[(y1c * 24 + x1c) * 64];
    float top = v00 + fx * (v01 - v00);
    float bot = v10 + fx * (v11 - v10);
    float val = top + fy * (bot - top);

    g_v2h[(size_t)col * N_TOK + n] = __float2half_rn(val);
}

// ---------------- kernel 2: per-cluster feature sums (smem-staged) ----------
__global__ __launch_bounds__(256) void k_csum(const float* __restrict__ x,
                                              const int* __restrict__ idx) {
    __shared__ float sacc[NCLU * 256];           // 32 KB
    __shared__ int sidx[256];
    int t = threadIdx.x;
    int r0 = blockIdx.x * 256;
    int c0 = blockIdx.y * 256;

#pragma unroll
    for (int c = 0; c < NCLU; c++) sacc[c * 256 + t] = 0.f;
    sidx[t] = idx[r0 + t];
    __syncthreads();

    // column t is owned by thread t -> no concurrent writers, plain RMW
    const float* xp = x + (size_t)r0 * CDIM + c0 + t;
#pragma unroll 4
    for (int r = 0; r < 256; r++) {
        int cl = sidx[r];
        sacc[cl * 256 + t] += xp[(size_t)r * CDIM];
    }
    __syncthreads();

#pragma unroll
    for (int c = 0; c < NCLU; c++)
        atomicAdd(&g_csum[c * CDIM + c0 + t], sacc[c * 256 + t]);
}

// ---------------- kernel 3: proxy + normalization (fp16 hi/lo out) ----------
__global__ __launch_bounds__(256) void k_proxy(const float* __restrict__ x,
                                               const int* __restrict__ idx) {
    __shared__ float red[256];
    int i = blockIdx.x, t = threadIdx.x;
    int ci = __ldg(&idx[i]);
    int b = i >> 10, s = i & 1023, r = s >> 5, c = s & 31;

    int nb[8];
    int nnb = 0;
#pragma unroll
    for (int dr = -1; dr <= 1; dr++) {
#pragma unroll
        for (int dc = -1; dc <= 1; dc++) {
            if (dr == 0 && dc == 0) continue;
            int rr = r + dr, cc = c + dc;
            if (rr >= 0 && rr < 32 && cc >= 0 && cc < 32) {
                int j = (b << 10) + (rr << 5) + cc;
                if (__ldg(&idx[j]) != ci) nb[nnb++] = j;
            }
        }
    }

    float p[3], xi[3];
#pragma unroll
    for (int u = 0; u < 3; u++) {
        int col = t + u * 256;
        float v = g_csum[ci * CDIM + col];
        for (int q = 0; q < nnb; q++) v += x[nb[q] * CDIM + col];
        p[u] = v;
        xi[u] = x[i * CDIM + col];
    }

    float ssp = p[0] * p[0] + p[1] * p[1] + p[2] * p[2];
    float ssx = xi[0] * xi[0] + xi[1] * xi[1] + xi[2] * xi[2];

    red[t] = ssp; __syncthreads();
    for (int w = 128; w > 0; w >>= 1) { if (t < w) red[t] += red[t + w]; __syncthreads(); }
    float SSP = red[0]; __syncthreads();
    red[t] = ssx; __syncthreads();
    for (int w = 128; w > 0; w >>= 1) { if (t < w) red[t] += red[t + w]; __syncthreads(); }
    float SSX = red[0];

    float ip = 1.f / fmaxf(sqrtf(SSP), 1e-12f);
    float ix = 1.f / fmaxf(sqrtf(SSX), 1e-12f);
#pragma unroll
    for (int u = 0; u < 3; u++) {
        int col = t + u * 256;
        float q = p[u] * ip;
        float k = xi[u] * ix;
        __half qh = __float2half_rn(q);
        g_qnh[i * CDIM + col] = qh;
        g_qnl[i * CDIM + col] = __float2half_rn(q - __half2float(qh));
        g_knh[i * CDIM + col] = __float2half_rn(k);   // B side: hi only
    }
}

// ---------------- split-fp16 HMMA GEMM: C[M][N] = A[M][K] * B[N][K]^T -------
// 2 MMAs per tile: Ah*Bh + Al*Bh  (= A*Bh exactly; dropped A*Bl ~1e-5)
// MODE 0: SIM = QN @ KN^T  (K=768,  NTILE=64)  -> g_sim fp32; 2048 CTAs
// MODE 1: OUT = P  @ V2    (K=4096, NTILE=96)  -> scatter rows; 256 CTAs
// CTA tile 128 x NTILE, 8 warps (4x2), K-chunk 32, 3-stage cp.async pipeline
// with ONE __syncthreads per chunk, occ 2. XOR swizzle sw(r,c16)=c16^((r>>1)&3).
// B row index is plain lr guarded by lr < NTILE (NTILE=96 not a power of 2!).
template <int MODE, int NTILE>
__global__ __launch_bounds__(256, 2)
void k_gemm_mma(float* __restrict__ outp) {
    extern __shared__ char smemc[];
    const int K = (MODE == 0) ? CDIM : N_TOK;
    const int NK = K / 32;
    const int NP = NTILE / 32;          // 16-row LDSM groups per warp-col
    const int NT = 2 * NP;              // 8-col accum tiles per warp
    const int BH_OFF = 16384;
    const int STAGE = 16384 + NTILE * 64;

    const __half* Ah = (MODE == 0) ? g_qnh : g_ph;
    const __half* Al = (MODE == 0) ? g_qnl : g_pl;
    const __half* Bh = (MODE == 0) ? g_knh : g_v2h;

    int tid = threadIdx.x;
    int bx = blockIdx.x, by = blockIdx.y;
    uint32_t sb = smem_u32(smemc);

    // ---- cp.async lane mapping: 2 threads/row, 2x16B each ----
    int lr = tid >> 1;                       // 0..127
    int lc0 = (tid & 1) * 2;                 // 16B-unit col 0 or 2
    size_t ga = (size_t)(by * 128 + lr) * K;
    size_t gb = (size_t)(bx * NTILE + lr) * K;   // only used under lr < NTILE
    int xr = (lr >> 1) & 3;
    uint32_t so0 = lr * 64 + (((lc0 + 0) ^ xr) << 4);
    uint32_t so1 = lr * 64 + (((lc0 + 1) ^ xr) << 4);

    // ---- ldmatrix lane mapping ----
    int l = tid & 31, w = tid >> 5;
    int wm = w & 3, wn = w >> 2;             // warp tile: rows wm*32, cols wn*(NTILE/2)
    int ra = wm * 32 + (l & 15);
    int xa = (ra >> 1) & 3;
    int ab = l >> 4;
    uint32_t aoff = (uint32_t)ra * 64;
    int rb = wn * (NTILE / 2) + (l & 7) + ((l >> 4) & 1) * 8;
    int xb = (rb >> 1) & 3;
    int bb = (l >> 3) & 1;
    uint32_t boff = (uint32_t)rb * 64;

    float acc[2][NT][4];
#pragma unroll
    for (int mt = 0; mt < 2; mt++)
#pragma unroll
        for (int nt = 0; nt < NT; nt++)
#pragma unroll
            for (int q = 0; q < 4; q++) acc[mt][nt][q] = 0.f;

#define ISSUE(kt_, s_) do {                                                    \
        uint32_t base_ = sb + (uint32_t)(s_) * STAGE;                          \
        const __half* pa_  = Ah + ga + (kt_) * 32 + lc0 * 8;                   \
        const __half* pal_ = Al + ga + (kt_) * 32 + lc0 * 8;                   \
        CPA16(base_ + so0, pa_);           CPA16(base_ + so1, pa_ + 8);        \
        CPA16(base_ + 8192 + so0, pal_);   CPA16(base_ + 8192 + so1, pal_ + 8);\
        if (lr < NTILE) {                                                      \
            const __half* pb_ = Bh + gb + (kt_) * 32 + lc0 * 8;                \
            CPA16(base_ + BH_OFF + so0, pb_);                                  \
            CPA16(base_ + BH_OFF + so1, pb_ + 8);                              \
        }                                                                      \
        CP_COMMIT();                                                           \
    } while (0)

    ISSUE(0, 0);
    ISSUE(1, 1);

    int scur = 0;    // stage of chunk kt
    int snx2 = 2;    // stage for chunk kt+2
#pragma unroll 1
    for (int kt = 0; kt < NK; kt++) {
        if (kt == NK - 1) { CP_WAIT(0); } else { CP_WAIT(1); }
        __syncthreads();
        // stage snx2 was last read at iteration kt-1; the barrier above
        // ordered those reads -> safe to overwrite, no second barrier needed.
        if (kt + 2 < NK) ISSUE(kt + 2, snx2);

        uint32_t st = sb + (uint32_t)scur * STAGE;
#pragma unroll
        for (int k16 = 0; k16 < 2; k16++) {
            uint32_t ah[2][4], al2[2][4];
#pragma unroll
            for (int mt = 0; mt < 2; mt++) {
                uint32_t ad = st + aoff + mt * 1024 + ((((2 * k16 + ab)) ^ xa) << 4);
                LDSM_X4(ah[mt][0], ah[mt][1], ah[mt][2], ah[mt][3], ad);
                LDSM_X4(al2[mt][0], al2[mt][1], al2[mt][2], al2[mt][3], ad + 8192);
            }
#pragma unroll
            for (int np = 0; np < NP; np++) {
                uint32_t bh[4];
                uint32_t bd = st + BH_OFF + boff + np * 1024 + ((((2 * k16 + bb)) ^ xb) << 4);
                LDSM_X4(bh[0], bh[1], bh[2], bh[3], bd);
#pragma unroll
                for (int mt = 0; mt < 2; mt++) {
#pragma unroll
                    for (int h = 0; h < 2; h++) {
                        int nt = np * 2 + h, h2 = h * 2;
                        float* C = acc[mt][nt];
                        MMA_F16(C[0], C[1], C[2], C[3],
                                ah[mt][0], ah[mt][1], ah[mt][2], ah[mt][3],
                                bh[h2], bh[h2 + 1]);
                        MMA_F16(C[0], C[1], C[2], C[3],
                                al2[mt][0], al2[mt][1], al2[mt][2], al2[mt][3],
                                bh[h2], bh[h2 + 1]);
                    }
                }
            }
        }
        scur = (scur == 2) ? 0 : scur + 1;
        snx2 = (snx2 == 2) ? 0 : snx2 + 1;
    }
#undef ISSUE

    // ---- epilogue ----
    int l4 = l >> 2, l2 = (l & 3) * 2;
#pragma unroll
    for (int mt = 0; mt < 2; mt++) {
#pragma unroll
        for (int nt = 0; nt < NT; nt++) {
            int row0 = by * 128 + wm * 32 + mt * 16 + l4;
            int col = bx * NTILE + wn * (NTILE / 2) + nt * 8 + l2;
            float2 v0 = make_float2(acc[mt][nt][0], acc[mt][nt][1]);
            float2 v1 = make_float2(acc[mt][nt][2], acc[mt][nt][3]);
            if (MODE == 0) {
                *(float2*)(g_sim + (size_t)row0 * N_TOK + col) = v0;
                *(float2*)(g_sim + (size_t)(row0 + 8) * N_TOK + col) = v1;
            } else {
                int o0 = (row0 & 1023) * 4 + (row0 >> 10);          // s*B + b
                int o1 = ((row0 + 8) & 1023) * 4 + ((row0 + 8) >> 10);
                *(float2*)(outp + (size_t)o0 * CDIM + col) = v0;
                *(float2*)(outp + (size_t)o1 * CDIM + col) = v1;
            }
        }
    }
}

// ---------------- block reductions (8 warps) ----------------
__device__ __forceinline__ float bred_sum(float v, float* wred, int t) {
#pragma unroll
    for (int o = 16; o > 0; o >>= 1) v += __shfl_xor_sync(0xffffffffu, v, o);
    __syncthreads();
    if ((t & 31) == 0) wred[t >> 5] = v;
    __syncthreads();
    float s = 0.f;
#pragma unroll
    for (int i = 0; i < 8; i++) s += wred[i];
    return s;
}
__device__ __forceinline__ float bred_max(float v, float* wred, int t) {
#pragma unroll
    for (int o = 16; o > 0; o >>= 1) v = fmaxf(v, __shfl_xor_sync(0xffffffffu, v, o));
    __syncthreads();
    if ((t & 31) == 0) wred[t >> 5] = v;
    __syncthreads();
    float s = -3.402823466e38f;
#pragma unroll
    for (int i = 0; i < 8; i++) s = fmaxf(s, wred[i]);
    return s;
}

// ---------------- softmax: token_norm + cut + softmax -> fp16 hi/lo probs ---
// Row kept entirely in registers (16 floats/thread); FFMA-poly exp (no MUFU).
__global__ __launch_bounds__(256) void k_softmax() {
    __shared__ float wred[8];
    int row = blockIdx.x, t = threadIdx.x;
    const float* Rp = g_sim + (size_t)row * N_TOK;

    float4 va[4];
    float s = 0.f;
#pragma unroll
    for (int u = 0; u < 4; u++) {
        va[u] = ((const float4*)Rp)[t + u * 256];
        s += (va[u].x + va[u].y) + (va[u].z + va[u].w);
    }
    float mean = fmaxf(bred_sum(s, wred, t) * (1.f / 4096.f), 0.f);

    float sub = mean * 1.2f;
    float mx = -3.402823466e38f;
#pragma unroll
    for (int u = 0; u < 4; u++) {
        va[u].x = (va[u].x - sub) * 3.0f; va[u].y = (va[u].y - sub) * 3.0f;
        va[u].z = (va[u].z - sub) * 3.0f; va[u].w = (va[u].w - sub) * 3.0f;
        mx = fmaxf(mx, fmaxf(fmaxf(va[u].x, va[u].y), fmaxf(va[u].z, va[u].w)));
    }
    float M = bred_max(mx, wred, t);

    float cut = fminf(M, 0.1f);
    const float invT = 1.f / 0.07f;
    float zs = 0.f;
#pragma unroll
    for (int u = 0; u < 4; u++) {
        va[u].x = (va[u].x < cut) ? 0.f : fexp((va[u].x - M) * invT);
        va[u].y = (va[u].y < cut) ? 0.f : fexp((va[u].y - M) * invT);
        va[u].z = (va[u].z < cut) ? 0.f : fexp((va[u].z - M) * invT);
        va[u].w = (va[u].w < cut) ? 0.f : fexp((va[u].w - M) * invT);
        zs += (va[u].x + va[u].y) + (va[u].z + va[u].w);
    }
    float inv = 1.f / bred_sum(zs, wred, t);

    __half* Ph = g_ph + (size_t)row * N_TOK;
    __half* Pl = g_pl + (size_t)row * N_TOK;
#pragma unroll
    for (int u = 0; u < 4; u++) {
        int c4 = t + u * 256;
        float x0 = va[u].x * inv, x1 = va[u].y * inv;
        float x2 = va[u].z * inv, x3 = va[u].w * inv;
        __half h0 = __float2half_rn(x0);
        __half h1 = __float2half_rn(x1);
        __half h2 = __float2half_rn(x2);
        __half h3 = __float2half_rn(x3);
        *(__half2*)(Ph + c4 * 4)     = __halves2half2(h0, h1);
        *(__half2*)(Ph + c4 * 4 + 2) = __halves2half2(h2, h3);
        __half l0 = __float2half_rn(x0 - __half2float(h0));
        __half l1 = __float2half_rn(x1 - __half2float(h1));
        __half l2b = __float2half_rn(x2 - __half2float(h2));
        __half l3 = __float2half_rn(x3 - __half2float(h3));
        *(__half2*)(Pl + c4 * 4)     = __halves2half2(l0, l1);
        *(__half2*)(Pl + c4 * 4 + 2) = __halves2half2(l2b, l3);
    }
}

// ---------------- launch ----------------
extern "C" void kernel_launch(void* const* d_in, const int* in_sizes, int n_in,
                              void* d_out, int out_size) {
    const float* ex = nullptr;
    const float* vext = nullptr;
    const int* idx = nullptr;
    for (int i = 0; i < n_in; i++) {
        if (in_sizes[i] == 4096) idx = (const int*)d_in[i];
        else if (in_sizes[i] == 2 * 2 * 1024 * 768) ex = (const float*)d_in[i];
        else if (in_sizes[i] == 48 * 24 * 24 * 64) vext = (const float*)d_in[i];
    }
    if (!ex || !vext || !idx) return;
    float* out = (float*)d_out;

    const int SMEM_G1 = 3 * (16384 + 64 * 64);  // NTILE=64, 3 stages (60 KB)
    const int SMEM_G2 = 3 * (16384 + 96 * 64);  // NTILE=96, 3 stages (66 KB)
    cudaFuncSetAttribute(k_gemm_mma<0, 64>, cudaFuncAttributeMaxDynamicSharedMemorySize, SMEM_G1);
    cudaFuncSetAttribute(k_gemm_mma<1, 96>, cudaFuncAttributeMaxDynamicSharedMemorySize, SMEM_G2);

    // Launch order puts k_gemm_mma<0> at slot #4 (the ncu capture position).
    k_resize<<<dim3(768, 16), 256>>>(vext);      // also zeroes g_csum
    k_csum<<<dim3(16, 3), 256>>>(ex, idx);
    k_proxy<<<N_TOK, 256>>>(ex, idx);
    k_gemm_mma<0, 64><<<dim3(64, 32), 256, SMEM_G1>>>(out);
    k_softmax<<<N_TOK, 256>>>();
    k_gemm_mma<1, 96><<<dim3(8, 32), 256, SMEM_G2>>>(out);
}

// round 17
// speedup vs baseline: 3.1453x; 1.0030x over previous
#include <cuda_runtime.h>
#include <cuda_fp16.h>
#include <cstdint>
#include <math.h>

// ---------------- problem constants ----------------
#define N_TOK 4096     // B*S
#define CDIM  768      // C = nh*Dh
#define NCLU  32

// ---------------- scratch (static device memory; no allocs allowed) --------
// Split-fp16 scheme: x = h + l, h=fp16(x), l=fp16(x-h).
// GEMM computes A_h*B_h + A_l*B_h = A*B_h exactly; dropped term A*l_B has
// random-sum sd ~2^-12*|A||B| ~ 1e-5 -> B-side needs NO low half at all.
__device__ __align__(256) float g_csum[NCLU * CDIM];
__device__ __align__(256) __half g_qnh[N_TOK * CDIM];          // l2norm(proxy) hi
__device__ __align__(256) __half g_qnl[N_TOK * CDIM];          // lo residual
__device__ __align__(256) __half g_knh[N_TOK * CDIM];          // l2norm(x), single fp16
__device__ __align__(256) __half g_v2h[CDIM * N_TOK];          // resized V^T, single fp16
__device__ __align__(256) float g_sim[(size_t)N_TOK * N_TOK];  // similarity (fp32)
__device__ __align__(256) __half g_ph[(size_t)N_TOK * N_TOK];  // probs hi
__device__ __align__(256) __half g_pl[(size_t)N_TOK * N_TOK];  // probs lo

// ---------------- PTX helpers (all baseline sm_80/89 features) -------------
__device__ __forceinline__ uint32_t smem_u32(const void* p) {
    uint32_t a;
    asm("{ .reg .u64 t; cvta.to.shared.u64 t, %1; cvt.u32.u64 %0, t; }" : "=r"(a) : "l"(p));
    return a;
}
#define CPA16(dst, src) \
    asm volatile("cp.async.cg.shared.global [%0], [%1], 16;" :: "r"(dst), "l"(src))
#define CP_COMMIT() asm volatile("cp.async.commit_group;")
#define CP_WAIT(n)  asm volatile("cp.async.wait_group %0;" :: "n"(n))

#define LDSM_X4(r0, r1, r2, r3, a) \
    asm volatile("ldmatrix.sync.aligned.m8n8.x4.shared.b16 {%0,%1,%2,%3}, [%4];" \
                 : "=r"(r0), "=r"(r1), "=r"(r2), "=r"(r3) : "r"(a))

#define MMA_F16(c0, c1, c2, c3, a0, a1, a2, a3, b0, b1) \
    asm volatile("mma.sync.aligned.m16n8k16.row.col.f32.f16.f16.f32 " \
                 "{%0,%1,%2,%3}, {%4,%5,%6,%7}, {%8,%9}, {%0,%1,%2,%3};" \
                 : "+f"(c0), "+f"(c1), "+f"(c2), "+f"(c3) \
                 : "r"(a0), "r"(a1), "r"(a2), "r"(a3), "r"(b0), "r"(b1))

// FFMA-only exp for t <= 0 (rel err ~3e-7): exp(t) = 2^n * poly(f)
__device__ __forceinline__ float fexp(float t) {
    float z = t * 1.4426950408889634f;      // log2(e)
    z = fmaxf(z, -126.0f);
    float n = floorf(z);
    float f = z - n;
    float p = 1.33336498e-3f;
    p = fmaf(p, f, 9.61817017e-3f);
    p = fmaf(p, f, 5.55036049e-2f);
    p = fmaf(p, f, 2.40226507e-1f);
    p = fmaf(p, f, 6.93147182e-1f);
    p = fmaf(p, f, 1.0f);
    int ni = (int)n;
    float sc = __int_as_float((ni + 127) << 23);
    return p * sc;
}

// ---------------- kernel 1: bilinear resize 24x24 -> 32x32 (writes V2^T) ----
// Also zeroes g_csum (fused so k_gemm1 lands on ncu's capture slot #4).
__global__ void k_resize(const float* __restrict__ vext) {
    if (blockIdx.y == 0 && blockIdx.x < 96) {
        g_csum[blockIdx.x * 256 + threadIdx.x] = 0.f;
    }
    int col = blockIdx.x;                        // 0..767
    int n = blockIdx.y * 256 + threadIdx.x;      // 0..4095
    int h = col >> 6, d = col & 63;
    int b = n >> 10, s = n & 1023, yy = s >> 5, xx = s & 31;

    float sy = 0.75f * (float)yy - 0.125f;
    float sx = 0.75f * (float)xx - 0.125f;
    float fy0 = floorf(sy), fx0 = floorf(sx);
    int y0 = (int)fy0, x0 = (int)fx0;
    float fy = sy - fy0, fx = sx - fx0;
    int y0c = max(y0, 0), y1c = min(y0 + 1, 23);
    int x0c = max(x0, 0), x1c = min(x0 + 1, 23);

    const float* base = vext + ((size_t)(b * 12 + h)) * (24 * 24 * 64) + d;
    float v00 = base[(y0c * 24 + x0c) * 64];
    float v01 = base[(y0c * 24 + x1c) * 64];
    float v10 = base[(y1c * 24 + x0c) * 64];
    float v11 = base[(y1c * 24 + x1c) * 64];
    float top = v00 + fx * (v01 - v00);
    float bot = v10 + fx * (v11 - v10);
    float val = top + fy * (bot - top);

    g_v2h[(size_t)col * N_TOK + n] = __float2half_rn(val);
}

// ---------------- kernel 2: per-cluster feature sums (smem-staged) ----------
__global__ __launch_bounds__(256) void k_csum(const float* __restrict__ x,
                                              const int* __restrict__ idx) {
    __shared__ float sacc[NCLU * 256];           // 32 KB
    __shared__ int sidx[256];
    int t = threadIdx.x;
    int r0 = blockIdx.x * 256;
    int c0 = blockIdx.y * 256;

#pragma unroll
    for (int c = 0; c < NCLU; c++) sacc[c * 256 + t] = 0.f;
    sidx[t] = idx[r0 + t];
    __syncthreads();

    // column t is owned by thread t -> no concurrent writers, plain RMW
    const float* xp = x + (size_t)r0 * CDIM + c0 + t;
#pragma unroll 4
    for (int r = 0; r < 256; r++) {
        int cl = sidx[r];
        sacc[cl * 256 + t] += xp[(size_t)r * CDIM];
    }
    __syncthreads();

#pragma unroll
    for (int c = 0; c < NCLU; c++)
        atomicAdd(&g_csum[c * CDIM + c0 + t], sacc[c * 256 + t]);
}

// ---------------- kernel 3: proxy + normalization (fp16 hi/lo out) ----------
__global__ __launch_bounds__(256) void k_proxy(const float* __restrict__ x,
                                               const int* __restrict__ idx) {
    __shared__ float red[256];
    int i = blockIdx.x, t = threadIdx.x;
    int ci = __ldg(&idx[i]);
    int b = i >> 10, s = i & 1023, r = s >> 5, c = s & 31;

    int nb[8];
    int nnb = 0;
#pragma unroll
    for (int dr = -1; dr <= 1; dr++) {
#pragma unroll
        for (int dc = -1; dc <= 1; dc++) {
            if (dr == 0 && dc == 0) continue;
            int rr = r + dr, cc = c + dc;
            if (rr >= 0 && rr < 32 && cc >= 0 && cc < 32) {
                int j = (b << 10) + (rr << 5) + cc;
                if (__ldg(&idx[j]) != ci) nb[nnb++] = j;
            }
        }
    }

    float p[3], xi[3];
#pragma unroll
    for (int u = 0; u < 3; u++) {
        int col = t + u * 256;
        float v = g_csum[ci * CDIM + col];
        for (int q = 0; q < nnb; q++) v += x[nb[q] * CDIM + col];
        p[u] = v;
        xi[u] = x[i * CDIM + col];
    }

    float ssp = p[0] * p[0] + p[1] * p[1] + p[2] * p[2];
    float ssx = xi[0] * xi[0] + xi[1] * xi[1] + xi[2] * xi[2];

    red[t] = ssp; __syncthreads();
    for (int w = 128; w > 0; w >>= 1) { if (t < w) red[t] += red[t + w]; __syncthreads(); }
    float SSP = red[0]; __syncthreads();
    red[t] = ssx; __syncthreads();
    for (int w = 128; w > 0; w >>= 1) { if (t < w) red[t] += red[t + w]; __syncthreads(); }
    float SSX = red[0];

    float ip = 1.f / fmaxf(sqrtf(SSP), 1e-12f);
    float ix = 1.f / fmaxf(sqrtf(SSX), 1e-12f);
#pragma unroll
    for (int u = 0; u < 3; u++) {
        int col = t + u * 256;
        float q = p[u] * ip;
        float k = xi[u] * ix;
        __half qh = __float2half_rn(q);
        g_qnh[i * CDIM + col] = qh;
        g_qnl[i * CDIM + col] = __float2half_rn(q - __half2float(qh));
        g_knh[i * CDIM + col] = __float2half_rn(k);   // B side: hi only
    }
}

// ---------------- split-fp16 HMMA GEMM: C[M][N] = A[M][K] * B[N][K]^T -------
// 2 MMAs per tile: Ah*Bh + Al*Bh  (= A*Bh exactly; dropped A*Bl ~1e-5)
// MODE 0: SIM = QN @ KN^T  (K=768,  NTILE=64, occ 3) -> g_sim fp32; 2048 CTAs
//         R16 ncu: tensor=50.4% at occ 2 (23.9%), L1=55% -> occupancy-bound;
//         occ 3 (regs capped 93->85, smem 3x20KB x3 = 180KB) feeds the pipe.
// MODE 1: OUT = P  @ V2    (K=4096, NTILE=96, occ 2) -> scatter rows; 256 CTAs
//         (already fully resident in one wave at occ 2; occ 3 would spill acc)
// CTA tile 128 x NTILE, 8 warps (4x2), K-chunk 32, 3-stage cp.async pipeline
// with ONE __syncthreads per chunk. XOR swizzle sw(r,c16)=c16^((r>>1)&3).
// B row index is plain lr guarded by lr < NTILE (NTILE=96 not a power of 2!).
template <int MODE, int NTILE>
__global__ __launch_bounds__(256, (MODE == 0) ? 3 : 2)
void k_gemm_mma(float* __restrict__ outp) {
    extern __shared__ char smemc[];
    const int K = (MODE == 0) ? CDIM : N_TOK;
    const int NK = K / 32;
    const int NP = NTILE / 32;          // 16-row LDSM groups per warp-col
    const int NT = 2 * NP;              // 8-col accum tiles per warp
    const int BH_OFF = 16384;
    const int STAGE = 16384 + NTILE * 64;

    const __half* Ah = (MODE == 0) ? g_qnh : g_ph;
    const __half* Al = (MODE == 0) ? g_qnl : g_pl;
    const __half* Bh = (MODE == 0) ? g_knh : g_v2h;

    int tid = threadIdx.x;
    int bx = blockIdx.x, by = blockIdx.y;
    uint32_t sb = smem_u32(smemc);

    // ---- cp.async lane mapping: 2 threads/row, 2x16B each ----
    int lr = tid >> 1;                       // 0..127
    int lc0 = (tid & 1) * 2;                 // 16B-unit col 0 or 2
    size_t ga = (size_t)(by * 128 + lr) * K;
    size_t gb = (size_t)(bx * NTILE + lr) * K;   // only used under lr < NTILE
    int xr = (lr >> 1) & 3;
    uint32_t so0 = lr * 64 + (((lc0 + 0) ^ xr) << 4);
    uint32_t so1 = lr * 64 + (((lc0 + 1) ^ xr) << 4);

    // ---- ldmatrix lane mapping ----
    int l = tid & 31, w = tid >> 5;
    int wm = w & 3, wn = w >> 2;             // warp tile: rows wm*32, cols wn*(NTILE/2)
    int ra = wm * 32 + (l & 15);
    int xa = (ra >> 1) & 3;
    int ab = l >> 4;
    uint32_t aoff = (uint32_t)ra * 64;
    int rb = wn * (NTILE / 2) + (l & 7) + ((l >> 4) & 1) * 8;
    int xb = (rb >> 1) & 3;
    int bb = (l >> 3) & 1;
    uint32_t boff = (uint32_t)rb * 64;

    float acc[2][NT][4];
#pragma unroll
    for (int mt = 0; mt < 2; mt++)
#pragma unroll
        for (int nt = 0; nt < NT; nt++)
#pragma unroll
            for (int q = 0; q < 4; q++) acc[mt][nt][q] = 0.f;

#define ISSUE(kt_, s_) do {                                                    \
        uint32_t base_ = sb + (uint32_t)(s_) * STAGE;                          \
        const __half* pa_  = Ah + ga + (kt_) * 32 + lc0 * 8;                   \
        const __half* pal_ = Al + ga + (kt_) * 32 + lc0 * 8;                   \
        CPA16(base_ + so0, pa_);           CPA16(base_ + so1, pa_ + 8);        \
        CPA16(base_ + 8192 + so0, pal_);   CPA16(base_ + 8192 + so1, pal_ + 8);\
        if (lr < NTILE) {                                                      \
            const __half* pb_ = Bh + gb + (kt_) * 32 + lc0 * 8;                \
            CPA16(base_ + BH_OFF + so0, pb_);                                  \
            CPA16(base_ + BH_OFF + so1, pb_ + 8);                              \
        }                                                                      \
        CP_COMMIT();                                                           \
    } while (0)

    ISSUE(0, 0);
    ISSUE(1, 1);

    int scur = 0;    // stage of chunk kt
    int snx2 = 2;    // stage for chunk kt+2
#pragma unroll 1
    for (int kt = 0; kt < NK; kt++) {
        if (kt == NK - 1) { CP_WAIT(0); } else { CP_WAIT(1); }
        __syncthreads();
        // stage snx2 was last read at iteration kt-1; the barrier above
        // ordered those reads -> safe to overwrite, no second barrier needed.
        if (kt + 2 < NK) ISSUE(kt + 2, snx2);

        uint32_t st = sb + (uint32_t)scur * STAGE;
#pragma unroll
        for (int k16 = 0; k16 < 2; k16++) {
            uint32_t ah[2][4], al2[2][4];
#pragma unroll
            for (int mt = 0; mt < 2; mt++) {
                uint32_t ad = st + aoff + mt * 1024 + ((((2 * k16 + ab)) ^ xa) << 4);
                LDSM_X4(ah[mt][0], ah[mt][1], ah[mt][2], ah[mt][3], ad);
                LDSM_X4(al2[mt][0], al2[mt][1], al2[mt][2], al2[mt][3], ad + 8192);
            }
#pragma unroll
            for (int np = 0; np < NP; np++) {
                uint32_t bh[4];
                uint32_t bd = st + BH_OFF + boff + np * 1024 + ((((2 * k16 + bb)) ^ xb) << 4);
                LDSM_X4(bh[0], bh[1], bh[2], bh[3], bd);
#pragma unroll
                for (int mt = 0; mt < 2; mt++) {
#pragma unroll
                    for (int h = 0; h < 2; h++) {
                        int nt = np * 2 + h, h2 = h * 2;
                        float* C = acc[mt][nt];
                        MMA_F16(C[0], C[1], C[2], C[3],
                                ah[mt][0], ah[mt][1], ah[mt][2], ah[mt][3],
                                bh[h2], bh[h2 + 1]);
                        MMA_F16(C[0], C[1], C[2], C[3],
                                al2[mt][0], al2[mt][1], al2[mt][2], al2[mt][3],
                                bh[h2], bh[h2 + 1]);
                    }
                }
            }
        }
        scur = (scur == 2) ? 0 : scur + 1;
        snx2 = (snx2 == 2) ? 0 : snx2 + 1;
    }
#undef ISSUE

    // ---- epilogue ----
    int l4 = l >> 2, l2 = (l & 3) * 2;
#pragma unroll
    for (int mt = 0; mt < 2; mt++) {
#pragma unroll
        for (int nt = 0; nt < NT; nt++) {
            int row0 = by * 128 + wm * 32 + mt * 16 + l4;
            int col = bx * NTILE + wn * (NTILE / 2) + nt * 8 + l2;
            float2 v0 = make_float2(acc[mt][nt][0], acc[mt][nt][1]);
            float2 v1 = make_float2(acc[mt][nt][2], acc[mt][nt][3]);
            if (MODE == 0) {
                *(float2*)(g_sim + (size_t)row0 * N_TOK + col) = v0;
                *(float2*)(g_sim + (size_t)(row0 + 8) * N_TOK + col) = v1;
            } else {
                int o0 = (row0 & 1023) * 4 + (row0 >> 10);          // s*B + b
                int o1 = ((row0 + 8) & 1023) * 4 + ((row0 + 8) >> 10);
                *(float2*)(outp + (size_t)o0 * CDIM + col) = v0;
                *(float2*)(outp + (size_t)o1 * CDIM + col) = v1;
            }
        }
    }
}

// ---------------- block reductions (8 warps) ----------------
__device__ __forceinline__ float bred_sum(float v, float* wred, int t) {
#pragma unroll
    for (int o = 16; o > 0; o >>= 1) v += __shfl_xor_sync(0xffffffffu, v, o);
    __syncthreads();
    if ((t & 31) == 0) wred[t >> 5] = v;
    __syncthreads();
    float s = 0.f;
#pragma unroll
    for (int i = 0; i < 8; i++) s += wred[i];
    return s;
}
__device__ __forceinline__ float bred_max(float v, float* wred, int t) {
#pragma unroll
    for (int o = 16; o > 0; o >>= 1) v = fmaxf(v, __shfl_xor_sync(0xffffffffu, v, o));
    __syncthreads();
    if ((t & 31) == 0) wred[t >> 5] = v;
    __syncthreads();
    float s = -3.402823466e38f;
#pragma unroll
    for (int i = 0; i < 8; i++) s = fmaxf(s, wred[i]);
    return s;
}

// ---------------- softmax: token_norm + cut + softmax -> fp16 hi/lo probs ---
// Row kept entirely in registers (16 floats/thread); FFMA-poly exp (no MUFU).
__global__ __launch_bounds__(256) void k_softmax() {
    __shared__ float wred[8];
    int row = blockIdx.x, t = threadIdx.x;
    const float* Rp = g_sim + (size_t)row * N_TOK;

    float4 va[4];
    float s = 0.f;
#pragma unroll
    for (int u = 0; u < 4; u++) {
        va[u] = ((const float4*)Rp)[t + u * 256];
        s += (va[u].x + va[u].y) + (va[u].z + va[u].w);
    }
    float mean = fmaxf(bred_sum(s, wred, t) * (1.f / 4096.f), 0.f);

    float sub = mean * 1.2f;
    float mx = -3.402823466e38f;
#pragma unroll
    for (int u = 0; u < 4; u++) {
        va[u].x = (va[u].x - sub) * 3.0f; va[u].y = (va[u].y - sub) * 3.0f;
        va[u].z = (va[u].z - sub) * 3.0f; va[u].w = (va[u].w - sub) * 3.0f;
        mx = fmaxf(mx, fmaxf(fmaxf(va[u].x, va[u].y), fmaxf(va[u].z, va[u].w)));
    }
    float M = bred_max(mx, wred, t);

    float cut = fminf(M, 0.1f);
    const float invT = 1.f / 0.07f;
    float zs = 0.f;
#pragma unroll
    for (int u = 0; u < 4; u++) {
        va[u].x = (va[u].x < cut) ? 0.f : fexp((va[u].x - M) * invT);
        va[u].y = (va[u].y < cut) ? 0.f : fexp((va[u].y - M) * invT);
        va[u].z = (va[u].z < cut) ? 0.f : fexp((va[u].z - M) * invT);
        va[u].w = (va[u].w < cut) ? 0.f : fexp((va[u].w - M) * invT);
        zs += (va[u].x + va[u].y) + (va[u].z + va[u].w);
    }
    float inv = 1.f / bred_sum(zs, wred, t);

    __half* Ph = g_ph + (size_t)row * N_TOK;
    __half* Pl = g_pl + (size_t)row * N_TOK;
#pragma unroll
    for (int u = 0; u < 4; u++) {
        int c4 = t + u * 256;
        float x0 = va[u].x * inv, x1 = va[u].y * inv;
        float x2 = va[u].z * inv, x3 = va[u].w * inv;
        __half h0 = __float2half_rn(x0);
        __half h1 = __float2half_rn(x1);
        __half h2 = __float2half_rn(x2);
        __half h3 = __float2half_rn(x3);
        *(__half2*)(Ph + c4 * 4)     = __halves2half2(h0, h1);
        *(__half2*)(Ph + c4 * 4 + 2) = __halves2half2(h2, h3);
        __half l0 = __float2half_rn(x0 - __half2float(h0));
        __half l1 = __float2half_rn(x1 - __half2float(h1));
        __half l2b = __float2half_rn(x2 - __half2float(h2));
        __half l3 = __float2half_rn(x3 - __half2float(h3));
        *(__half2*)(Pl + c4 * 4)     = __halves2half2(l0, l1);
        *(__half2*)(Pl + c4 * 4 + 2) = __halves2half2(l2b, l3);
    }
}

// ---------------- launch ----------------
extern "C" void kernel_launch(void* const* d_in, const int* in_sizes, int n_in,
                              void* d_out, int out_size) {
    const float* ex = nullptr;
    const float* vext = nullptr;
    const int* idx = nullptr;
    for (int i = 0; i < n_in; i++) {
        if (in_sizes[i] == 4096) idx = (const int*)d_in[i];
        else if (in_sizes[i] == 2 * 2 * 1024 * 768) ex = (const float*)d_in[i];
        else if (in_sizes[i] == 48 * 24 * 24 * 64) vext = (const float*)d_in[i];
    }
    if (!ex || !vext || !idx) return;
    float* out = (float*)d_out;

    const int SMEM_G1 = 3 * (16384 + 64 * 64);  // NTILE=64, 3 stages (60 KB)
    const int SMEM_G2 = 3 * (16384 + 96 * 64);  // NTILE=96, 3 stages (66 KB)
    cudaFuncSetAttribute(k_gemm_mma<0, 64>, cudaFuncAttributeMaxDynamicSharedMemorySize, SMEM_G1);
    cudaFuncSetAttribute(k_gemm_mma<1, 96>, cudaFuncAttributeMaxDynamicSharedMemorySize, SMEM_G2);

    // Launch order puts k_gemm_mma<0> at slot #4 (the ncu capture position).
    k_resize<<<dim3(768, 16), 256>>>(vext);      // also zeroes g_csum
    k_csum<<<dim3(16, 3), 256>>>(ex, idx);
    k_proxy<<<N_TOK, 256>>>(ex, idx);
    k_gemm_mma<0, 64><<<dim3(64, 32), 256, SMEM_G1>>>(out);
    k_softmax<<<N_TOK, 256>>>();
    k_gemm_mma<1, 96><<<dim3(8, 32), 256, SMEM_G2>>>(out);
}